// round 2
// baseline (speedup 1.0000x reference)
#include <cuda_runtime.h>
#include <cstdint>

// Problem constants
#define H       30
#define BATCHN  16384
#define SEQ     784
#define NC      10

// Launch geometry: 1 warp handles 1 pair of batch elements (packed f32x2).
#define PAIRS    8          // pairs per block = warps per block
#define THREADS  256
#define TCHUNK   112        // time steps staged per chunk (784 = 7 * 112)
#define NCHUNK   7
#define XROW     18         // floats per time-row in xs (padded for bank spread)

typedef unsigned long long ull;

// ---- packed f32x2 helpers (FFMA2 path: 2 fp32 FMAs per instruction) ----
__device__ __forceinline__ ull ffma2(ull a, ull b, ull c) {
    ull d; asm("fma.rn.f32x2 %0, %1, %2, %3;" : "=l"(d) : "l"(a), "l"(b), "l"(c)); return d;
}
__device__ __forceinline__ ull fmul2(ull a, ull b) {
    ull d; asm("mul.rn.f32x2 %0, %1, %2;" : "=l"(d) : "l"(a), "l"(b)); return d;
}
__device__ __forceinline__ ull fadd2(ull a, ull b) {
    ull d; asm("add.rn.f32x2 %0, %1, %2;" : "=l"(d) : "l"(a), "l"(b)); return d;
}
__device__ __forceinline__ ull pack2(float lo, float hi) {
    ull d; asm("mov.b64 %0, {%1, %2};" : "=l"(d) : "f"(lo), "f"(hi)); return d;
}
__device__ __forceinline__ void unpack2(ull v, float& lo, float& hi) {
    asm("mov.b64 {%0, %1}, %2;" : "=f"(lo), "=f"(hi) : "l"(v));
}
__device__ __forceinline__ ull dup2(float v) { return pack2(v, v); }

__global__ __launch_bounds__(THREADS)
void rnn_modrelu_kernel(const float* __restrict__ inputs,   // [B, SEQ]
                        const float* __restrict__ W_ih,     // [H, 1]
                        const float* __restrict__ W_hh,     // [H, H]
                        const float* __restrict__ b_mod,    // [H]
                        const float* __restrict__ W_lin,    // [NC, H]
                        const float* __restrict__ b_lin,    // [NC]
                        float* __restrict__ out)            // [B, NC]
{
    // Staged inputs for this block's 16 batch rows, packed so that the two
    // batch elements of pair p sit adjacent: xs[i*XROW + 2p], xs[i*XROW + 2p+1].
    __shared__ __align__(16) float xs[TCHUNK * XROW];
    // Per-warp double-buffered hidden state, packed pair per entry.
    __shared__ __align__(16) ull h_sh[PAIRS][2][32];

    const int tid  = threadIdx.x;
    const int w    = tid >> 5;
    const int lane = tid & 31;
    const bool active = (lane < H);
    const int j = active ? lane : (H - 1);     // lanes 30/31 shadow row 29, never write

    const int pairG = blockIdx.x * PAIRS + w;  // global pair index
    const int b0 = pairG * 2;                  // first batch element of the pair

    // --- load per-lane weights into registers (row j of W_hh, duplicated-packed) ---
    const ull  wih = dup2(W_ih[j]);
    const float bj = b_mod[j];
    ull wrow[H];
#pragma unroll
    for (int k = 0; k < H; k++) wrow[k] = dup2(W_hh[j * H + k]);

    // init hidden state buffers to zero (h0 = 0)
    h_sh[w][0][lane] = 0ull;
    h_sh[w][1][lane] = 0ull;
    __syncwarp();

    const float* inBase0 = inputs + (size_t)(blockIdx.x * PAIRS * 2) * SEQ;

    for (int ch = 0; ch < NCHUNK; ch++) {
        __syncthreads();  // all warps done reading previous xs chunk
        // stage 16 rows x TCHUNK steps, interleaved by batch row
        const float* inBase = inBase0 + ch * TCHUNK;
        for (int e = tid; e < 16 * TCHUNK; e += THREADS) {
            int r = e / TCHUNK;          // local batch row 0..15
            int i = e - r * TCHUNK;      // time within chunk
            xs[i * XROW + r] = inBase[(size_t)r * SEQ + i];
        }
        __syncthreads();

#pragma unroll 2
        for (int i = 0; i < TCHUNK; i++) {
            const int rb = i & 1;        // chunk len even, so parity tracks i
            const ulonglong2* hp = (const ulonglong2*)&h_sh[w][rb][0];

            // packed inputs for this pair at step t (broadcast within warp)
            const ull x2 = *(const ull*)&xs[i * XROW + 2 * w];

            // z_j = x * w_ih[j] + sum_k W_hh[j][k] * h[k]   (two accumulator chains)
            ull acc0 = fmul2(x2, wih);
            ull acc1 = 0ull;
#pragma unroll
            for (int k = 0; k < H / 2; k++) {
                ulonglong2 hv = hp[k];                 // LDS.128, warp-broadcast
                acc0 = ffma2(wrow[2 * k],     hv.x, acc0);
                acc1 = ffma2(wrow[2 * k + 1], hv.y, acc1);
            }
            const ull z = fadd2(acc0, acc1);

            // modReLU: sign(z) * relu(|z| + b)
            float zl, zh; unpack2(z, zl, zh);
            const float ml = fmaxf(fabsf(zl) + bj, 0.0f);
            const float mh = fmaxf(fabsf(zh) + bj, 0.0f);
            const unsigned il = __float_as_uint(ml) | (__float_as_uint(zl) & 0x80000000u);
            const unsigned ih = __float_as_uint(mh) | (__float_as_uint(zh) & 0x80000000u);
            const ull hn = pack2(__uint_as_float(il), __uint_as_float(ih));

            if (active) h_sh[w][1 - rb][j] = hn;
            __syncwarp();   // orders prev writes before next reads AND prev reads before next writes
        }
    }

    // Final state is in buffer 0 (784 steps: last write lands in buf 0).
    const ulonglong2* hp = (const ulonglong2*)&h_sh[w][0][0];
    if (lane < NC) {
        const int c = lane;
        ull acc = dup2(b_lin[c]);
#pragma unroll
        for (int k = 0; k < H / 2; k++) {
            ulonglong2 hv = hp[k];
            acc = ffma2(dup2(W_lin[c * H + 2 * k]),     hv.x, acc);
            acc = ffma2(dup2(W_lin[c * H + 2 * k + 1]), hv.y, acc);
        }
        float lo, hi; unpack2(acc, lo, hi);
        out[(size_t)b0 * NC + c]       = lo;
        out[(size_t)(b0 + 1) * NC + c] = hi;
    }
}

extern "C" void kernel_launch(void* const* d_in, const int* in_sizes, int n_in,
                              void* d_out, int out_size) {
    const float* inputs = (const float*)d_in[0];
    const float* W_ih   = (const float*)d_in[1];
    const float* W_hh   = (const float*)d_in[2];
    const float* b_mod  = (const float*)d_in[3];
    const float* W_lin  = (const float*)d_in[4];
    const float* b_lin  = (const float*)d_in[5];
    float* out = (float*)d_out;

    const int nblocks = BATCHN / (2 * PAIRS);   // 1024
    rnn_modrelu_kernel<<<nblocks, THREADS>>>(inputs, W_ih, W_hh, b_mod,
                                             W_lin, b_lin, out);
}